// round 2
// baseline (speedup 1.0000x reference)
#include <cuda_runtime.h>

// WaveletTransformLayer: x (B=128, T=2048, F=32) fp32.
// Per (b,f) series: 3-level moving-average pyramid (w = 2, 4, 8),
// details + final approx concatenated, / T, per-series contiguous in output.

constexpr int B = 128;
constexpr int T = 2048;
constexpr int F = 32;

constexpr int N1 = T - 2 + 1;        // 2047
constexpr int N2 = N1 - 4 + 1;       // 2044
constexpr int N3 = N2 - 8 + 1;       // 2037
constexpr int OUT_PER = N1 + N2 + N3 + N3;  // 8165

__global__ __launch_bounds__(256, 8)
void wavelet_kernel(const float* __restrict__ x, float* __restrict__ out) {
    __shared__ float sa[T];
    __shared__ float sb[T];

    const int series = blockIdx.x;          // = b * F + f
    const int bb = series >> 5;             // / F
    const int f  = series & (F - 1);        // % F

    const float* xp = x + (size_t)bb * T * F + f;
    float* op = out + (size_t)series * OUT_PER;
    const float invT = 1.0f / (float)T;

    // Load series (strided gather; input fits in L2, re-read across the 32
    // sibling blocks of the same b hits L2 not DRAM).
    #pragma unroll
    for (int t = threadIdx.x; t < T; t += 256)
        sa[t] = xp[(size_t)t * F];
    __syncthreads();

    // Level 1: w = 2.  ma1[i] = (a[i]+a[i+1])/2, detail = a[i+1]-ma1.
    #pragma unroll
    for (int i = threadIdx.x; i < N1; i += 256) {
        float a0 = sa[i], a1 = sa[i + 1];
        float ma = (a0 + a1) * 0.5f;
        op[i] = (a1 - ma) * invT;
        sb[i] = ma;
    }
    __syncthreads();

    // Level 2: w = 4 over sb[0..N1).
    #pragma unroll
    for (int i = threadIdx.x; i < N2; i += 256) {
        float s = sb[i] + sb[i + 1] + sb[i + 2] + sb[i + 3];
        float ma = s * 0.25f;
        op[N1 + i] = (sb[i + 3] - ma) * invT;
        sa[i] = ma;  // reuse sa; input values no longer needed
    }
    __syncthreads();

    // Level 3: w = 8 over sa[0..N2). Emit detail and final approx.
    #pragma unroll
    for (int i = threadIdx.x; i < N3; i += 256) {
        float s = sa[i]     + sa[i + 1] + sa[i + 2] + sa[i + 3]
                + sa[i + 4] + sa[i + 5] + sa[i + 6] + sa[i + 7];
        float ma = s * 0.125f;
        op[N1 + N2 + i]      = (sa[i + 7] - ma) * invT;
        op[N1 + N2 + N3 + i] = ma * invT;
    }
}

extern "C" void kernel_launch(void* const* d_in, const int* in_sizes, int n_in,
                              void* d_out, int out_size) {
    const float* x = (const float*)d_in[0];
    float* out = (float*)d_out;
    wavelet_kernel<<<B * F, 256>>>(x, out);
}

// round 3
// speedup vs baseline: 1.8778x; 1.8778x over previous
#include <cuda_runtime.h>

// WaveletTransformLayer: x (B=128, T=2048, F=32) fp32.
// 3-level moving-average pyramid (w = 2, 4, 8) per (b,f) series.
// Tiled over T (halo = 11): block loads all 32 features coalesced,
// transposes to smem, each warp processes 4 features warp-privately.

constexpr int B = 128;
constexpr int T = 2048;
constexpr int F = 32;

constexpr int N1 = T - 1;            // 2047  (w=2)
constexpr int N2 = N1 - 3;           // 2044  (w=4)
constexpr int N3 = N2 - 7;           // 2037  (w=8)
constexpr int OUT_PER = N1 + N2 + 2 * N3;  // 8165

constexpr int TT = 128;              // time-tile
constexpr int NTILES = T / TT;       // 16
constexpr int HALO = 11;             // x support needed beyond tile: TT+11 samples
constexpr int ST = 141;              // smem row stride (odd -> conflict-free transpose)

__global__ __launch_bounds__(256, 6)
void wavelet_kernel(const float* __restrict__ x, float* __restrict__ out) {
    __shared__ float s_in[F * ST];   // x tile; reused for ma2 after level 2
    __shared__ float s_m1[F * ST];   // ma1

    const int tile = blockIdx.x & (NTILES - 1);
    const int b    = blockIdx.x >> 4;
    const int t0   = tile * TT;
    const int tid  = threadIdx.x;
    const int lane = tid & 31;
    const int w    = tid >> 5;       // warp id, 0..7

    // ---- Coalesced load + transpose: row j (time), lane = feature ----
    // Each warp-load reads one full 128 B line x[b, t0+j, 0..31].
    const float* xp = x + ((size_t)b * T + t0) * F;
    #pragma unroll
    for (int j = w; j < TT + HALO; j += 8) {
        float v = (t0 + j < T) ? xp[(size_t)j * F + lane] : 0.0f;
        s_in[lane * ST + j] = v;
    }
    __syncthreads();

    const float invT = 1.0f / (float)T;

    // ---- Warp-private pyramid: warp w owns features 4w .. 4w+3 ----
    #pragma unroll
    for (int ff = 0; ff < 4; ff++) {
        const int f = (w << 2) + ff;
        float* __restrict__ rin = s_in + f * ST;
        float* __restrict__ rm1 = s_m1 + f * ST;
        float* __restrict__ op  = out + (size_t)(b * F + f) * OUT_PER;

        // Level 1: w=2. ma1[j] needed for j < TT+10.
        #pragma unroll
        for (int j = lane; j < TT + 10; j += 32) {
            float a1 = rin[j + 1];
            float ma = (rin[j] + a1) * 0.5f;
            rm1[j] = ma;
            if (j < TT && t0 + j < N1)
                op[t0 + j] = (a1 - ma) * invT;
        }
        __syncwarp();

        // Level 2: w=4 over ma1. ma2[j] needed for j < TT+7; store into rin.
        #pragma unroll
        for (int j = lane; j < TT + 7; j += 32) {
            float m3 = rm1[j + 3];
            float ma = (rm1[j] + rm1[j + 1] + rm1[j + 2] + m3) * 0.25f;
            rin[j] = ma;
            if (j < TT && t0 + j < N2)
                op[N1 + t0 + j] = (m3 - ma) * invT;
        }
        __syncwarp();

        // Level 3: w=8 over ma2 (now in rin). Detail + final approx.
        #pragma unroll
        for (int j = lane; j < TT; j += 32) {
            float m7 = rin[j + 7];
            float s  = rin[j] + rin[j + 1] + rin[j + 2] + rin[j + 3]
                     + rin[j + 4] + rin[j + 5] + rin[j + 6] + m7;
            float ma = s * 0.125f;
            if (t0 + j < N3) {
                op[N1 + N2 + t0 + j]      = (m7 - ma) * invT;
                op[N1 + N2 + N3 + t0 + j] = ma * invT;
            }
        }
        __syncwarp();
    }
}

extern "C" void kernel_launch(void* const* d_in, const int* in_sizes, int n_in,
                              void* d_out, int out_size) {
    const float* x = (const float*)d_in[0];
    float* out = (float*)d_out;
    wavelet_kernel<<<B * NTILES, 256>>>(x, out);
}